// round 3
// baseline (speedup 1.0000x reference)
#include <cuda_runtime.h>
#include <cuda_bf16.h>

// GraphConv: out = segment_sum((x@W)[cols] * vals, rows) / norm + bias
//          = (segment_sum(x[cols] * vals, rows)) @ W / norm + bias   (linearity)
// Inputs (metadata order):
//  0: x        [100000,128] f32
//  1: weight   [128,128]    f32
//  2: bias     [128]        f32
//  3: adj_rows [3200000]    i32   (destination / segment id)
//  4: adj_cols [3200000]    i32   (source row)
//  5: adj_vals [3200000]    f32
//  6: norm     [100000,1]   f32
// out: [100000,128] f32

#define N_NODES 100000
#define N_EDGES 3200000
#define D 128
#define CAP 128            // max in-degree slots (Poisson(32), max ~60; big margin)
#define NODES_PER_BLK 64

// static device scratch (allocations are banned)
__device__ int  g_counts[N_NODES];                    // 0.4 MB
__device__ int2 g_edges[(size_t)N_NODES * CAP];       // 102.4 MB {col, val_bits}

// ---------------------------------------------------------------------------
// Kernel 1: bucket edges by destination row. 4 edges per thread for MLP.
// ---------------------------------------------------------------------------
__global__ __launch_bounds__(256) void place_kernel(
    const int* __restrict__ rows, const int* __restrict__ cols,
    const float* __restrict__ vals)
{
    const int t = blockIdx.x * blockDim.x + threadIdx.x;   // quad index
    if (t * 4 >= N_EDGES) return;

    const int4   r4 = __ldg(reinterpret_cast<const int4*>(rows) + t);
    const int4   c4 = __ldg(reinterpret_cast<const int4*>(cols) + t);
    const float4 v4 = __ldg(reinterpret_cast<const float4*>(vals) + t);

    // 4 independent atomics in flight
    const int s0 = atomicAdd(&g_counts[r4.x], 1);
    const int s1 = atomicAdd(&g_counts[r4.y], 1);
    const int s2 = atomicAdd(&g_counts[r4.z], 1);
    const int s3 = atomicAdd(&g_counts[r4.w], 1);

    if (s0 < CAP) g_edges[(size_t)r4.x * CAP + s0] = make_int2(c4.x, __float_as_int(v4.x));
    if (s1 < CAP) g_edges[(size_t)r4.y * CAP + s1] = make_int2(c4.y, __float_as_int(v4.y));
    if (s2 < CAP) g_edges[(size_t)r4.z * CAP + s2] = make_int2(c4.z, __float_as_int(v4.z));
    if (s3 < CAP) g_edges[(size_t)r4.w * CAP + s3] = make_int2(c4.w, __float_as_int(v4.w));
}

// ---------------------------------------------------------------------------
// Kernel 2 (fused): per block of 64 nodes:
//   phase 1: gather Y[n,:] = sum_e val_e * x[col_e,:]  into smem (warp/node)
//   phase 2: out[n,:] = (Y @ W) * inv_norm[n] + bias    (smem GEMM)
// smem: W 64KB + Y 64x132 (33.8KB) + invn  => ~97.3KB, 2 CTAs/SM.
// ---------------------------------------------------------------------------
__global__ __launch_bounds__(256, 2) void fused_kernel(
    const float* __restrict__ x, const float* __restrict__ w,
    const float* __restrict__ bias, const float* __restrict__ norm,
    float* __restrict__ out)
{
    extern __shared__ float sm[];
    float* Ws   = sm;                         // [128][128]  Ws[k*128+n]
    float* Ya   = sm + 16384;                 // [64][132]   Ya[r*132+k]
    float* invn = Ya + NODES_PER_BLK * 132;   // [64]

    const int tid  = threadIdx.x;
    const int lane = tid & 31;
    const int wid  = tid >> 5;
    const int node0 = blockIdx.x * NODES_PER_BLK;

    // --- load W into smem (coalesced, 16 float4 per thread) ---
    #pragma unroll
    for (int i = 0; i < 16; i++) {
        int idx = tid + i * 256;              // float4 index 0..4095
        reinterpret_cast<float4*>(Ws)[idx] =
            __ldg(reinterpret_cast<const float4*>(w) + idx);
    }

    // --- gather phase: warp handles nodes wid, wid+8, ... ---
    for (int n = wid; n < NODES_PER_BLK; n += 8) {
        const int g = node0 + n;
        float4 acc = make_float4(0.f, 0.f, 0.f, 0.f);
        if (g < N_NODES) {
            int deg = g_counts[g];
            if (deg > CAP) deg = CAP;
            const int2* ep = g_edges + (size_t)g * CAP;

            for (int j = 0; j < deg; j += 8) {
                int   c[8];
                float v[8];
                #pragma unroll
                for (int k = 0; k < 8; k++) {
                    int2 p = __ldg(ep + j + k);        // warp-uniform broadcast
                    bool ok = (j + k) < deg;
                    c[k] = ok ? p.x : 0;
                    v[k] = ok ? __int_as_float(p.y) : 0.0f;
                }
                float4 s[8];
                #pragma unroll
                for (int k = 0; k < 8; k++)
                    s[k] = __ldg(reinterpret_cast<const float4*>(x + (size_t)c[k] * D) + lane);
                #pragma unroll
                for (int k = 0; k < 8; k++) {
                    acc.x = fmaf(s[k].x, v[k], acc.x);
                    acc.y = fmaf(s[k].y, v[k], acc.y);
                    acc.z = fmaf(s[k].z, v[k], acc.z);
                    acc.w = fmaf(s[k].w, v[k], acc.w);
                }
            }
            if (lane == 0) invn[n] = 1.0f / __ldg(norm + g);
        }
        *reinterpret_cast<float4*>(&Ya[n * 132 + lane * 4]) = acc;
    }
    __syncthreads();

    // --- GEMM phase: block computes [64 x 128] = Ya[64x128] @ Ws[128x128] ---
    const int tr = tid >> 4;   // 0..15 -> rows tr*4 .. tr*4+3
    const int tc = tid & 15;   // 0..15 -> cols tc*8 .. tc*8+7
    float acc[4][8];
    #pragma unroll
    for (int i = 0; i < 4; i++)
        #pragma unroll
        for (int j = 0; j < 8; j++) acc[i][j] = 0.0f;

    #pragma unroll 8
    for (int k = 0; k < D; k++) {
        float a0 = Ya[(tr * 4 + 0) * 132 + k];
        float a1 = Ya[(tr * 4 + 1) * 132 + k];
        float a2 = Ya[(tr * 4 + 2) * 132 + k];
        float a3 = Ya[(tr * 4 + 3) * 132 + k];
        float4 b0 = *reinterpret_cast<float4*>(&Ws[k * 128 + tc * 8]);
        float4 b1 = *reinterpret_cast<float4*>(&Ws[k * 128 + tc * 8 + 4]);
        const float bb[8] = {b0.x, b0.y, b0.z, b0.w, b1.x, b1.y, b1.z, b1.w};
        const float aa[4] = {a0, a1, a2, a3};
        #pragma unroll
        for (int i = 0; i < 4; i++)
            #pragma unroll
            for (int j = 0; j < 8; j++)
                acc[i][j] = fmaf(aa[i], bb[j], acc[i][j]);
    }

    // --- epilogue: out = acc * invn + bias ---
    const float4 bi0 = __ldg(reinterpret_cast<const float4*>(bias + tc * 8));
    const float4 bi1 = __ldg(reinterpret_cast<const float4*>(bias + tc * 8 + 4));
    #pragma unroll
    for (int i = 0; i < 4; i++) {
        const int r = tr * 4 + i;
        const int g = node0 + r;
        if (g < N_NODES) {
            const float inv = invn[r];
            float4 o0, o1;
            o0.x = fmaf(acc[i][0], inv, bi0.x);
            o0.y = fmaf(acc[i][1], inv, bi0.y);
            o0.z = fmaf(acc[i][2], inv, bi0.z);
            o0.w = fmaf(acc[i][3], inv, bi0.w);
            o1.x = fmaf(acc[i][4], inv, bi1.x);
            o1.y = fmaf(acc[i][5], inv, bi1.y);
            o1.z = fmaf(acc[i][6], inv, bi1.z);
            o1.w = fmaf(acc[i][7], inv, bi1.w);
            float* dst = out + (size_t)g * D + tc * 8;
            *reinterpret_cast<float4*>(dst)     = o0;
            *reinterpret_cast<float4*>(dst + 4) = o1;
        }
    }
}

// ---------------------------------------------------------------------------
extern "C" void kernel_launch(void* const* d_in, const int* in_sizes, int n_in,
                              void* d_out, int out_size) {
    const float* x      = (const float*)d_in[0];
    const float* weight = (const float*)d_in[1];
    const float* bias   = (const float*)d_in[2];
    const int*   rows   = (const int*)  d_in[3];
    const int*   cols   = (const int*)  d_in[4];
    const float* vals   = (const float*)d_in[5];
    const float* norm   = (const float*)d_in[6];
    float*       out    = (float*)d_out;

    int* counts;
    cudaGetSymbolAddress((void**)&counts, g_counts);

    // zero bucket counters
    cudaMemsetAsync(counts, 0, N_NODES * sizeof(int));

    // bucket edges by destination (4 edges/thread)
    const int quads = N_EDGES / 4;
    place_kernel<<<(quads + 255) / 256, 256>>>(rows, cols, vals);

    // fused gather-aggregate + GEMM + epilogue
    const size_t smem_bytes = (16384 + NODES_PER_BLK * 132 + NODES_PER_BLK) * sizeof(float);
    cudaFuncSetAttribute(fused_kernel, cudaFuncAttributeMaxDynamicSharedMemorySize,
                         (int)smem_bytes);
    const int blocks = (N_NODES + NODES_PER_BLK - 1) / NODES_PER_BLK;
    fused_kernel<<<blocks, 256, smem_bytes>>>(x, weight, bias, norm, out);
}

// round 4
// speedup vs baseline: 1.1412x; 1.1412x over previous
#include <cuda_runtime.h>
#include <cuda_bf16.h>
#include <cstdint>

// GraphConv: out = segment_sum((x@W)[cols] * vals, rows) / norm + bias
// Inputs: x[100000,128] w[128,128] bias[128] rows[3.2M] cols[3.2M] vals[3.2M] norm[100000,1]
// out: [100000,128] f32

#define N_NODES 100000
#define N_EDGES 3200000
#define D 128
#define CAP 128

// static device scratch (allocations banned)
__device__ float g_support[(size_t)N_NODES * D];      // 51.2 MB
__device__ int   g_counts[N_NODES];                   // 0.4 MB
__device__ int2  g_edges[(size_t)N_NODES * CAP];      // 102.4 MB {col, val_bits}

// ---------------------------------------------------------------------------
// packed f32x2 helpers
// ---------------------------------------------------------------------------
__device__ __forceinline__ void fma2(unsigned long long& c,
                                     unsigned long long a, unsigned long long b) {
    asm("fma.rn.f32x2 %0, %1, %2, %0;" : "+l"(c) : "l"(a), "l"(b));
}
__device__ __forceinline__ void lds_v2u64(unsigned long long& p0, unsigned long long& p1,
                                          unsigned sa) {
    asm("ld.shared.v2.b64 {%0,%1}, [%2];" : "=l"(p0), "=l"(p1) : "r"(sa));
}
__device__ __forceinline__ void unpack2(float& lo, float& hi, unsigned long long p) {
    asm("mov.b64 {%0,%1}, %2;" : "=f"(lo), "=f"(hi) : "l"(p));
}

// ---------------------------------------------------------------------------
// Kernel 1: bucket edges by destination. 4 edges/thread for MLP.
// ---------------------------------------------------------------------------
__global__ __launch_bounds__(256) void place_kernel(
    const int* __restrict__ rows, const int* __restrict__ cols,
    const float* __restrict__ vals)
{
    const int t = blockIdx.x * blockDim.x + threadIdx.x;
    if (t * 4 >= N_EDGES) return;

    const int4   r4 = __ldg(reinterpret_cast<const int4*>(rows) + t);
    const int4   c4 = __ldg(reinterpret_cast<const int4*>(cols) + t);
    const float4 v4 = __ldg(reinterpret_cast<const float4*>(vals) + t);

    const int s0 = atomicAdd(&g_counts[r4.x], 1);
    const int s1 = atomicAdd(&g_counts[r4.y], 1);
    const int s2 = atomicAdd(&g_counts[r4.z], 1);
    const int s3 = atomicAdd(&g_counts[r4.w], 1);

    if (s0 < CAP) g_edges[(size_t)r4.x * CAP + s0] = make_int2(c4.x, __float_as_int(v4.x));
    if (s1 < CAP) g_edges[(size_t)r4.y * CAP + s1] = make_int2(c4.y, __float_as_int(v4.y));
    if (s2 < CAP) g_edges[(size_t)r4.z * CAP + s2] = make_int2(c4.z, __float_as_int(v4.z));
    if (s3 < CAP) g_edges[(size_t)r4.w * CAP + s3] = make_int2(c4.w, __float_as_int(v4.w));
}

// ---------------------------------------------------------------------------
// Kernel 2: half-N GEMM with packed f32x2 FMA.
// support[:, h*64 : h*64+64] = x @ W[:, h*64 : h*64+64]
// Block: 128 rows x 64 cols, BK=16, 256 threads.
// Thread micro-tile: 8 rows (as 4 packed row-pairs) x 4 cols.
// Bsd holds each W value DUPLICATED ({b,b}) so b-fragments load as v2.b64.
// ---------------------------------------------------------------------------
__global__ __launch_bounds__(256) void gemm_half_kernel(
    const float* __restrict__ x, const float* __restrict__ w,
    float* __restrict__ sup, int h)
{
    __shared__ float As[16][132];    // As[k][m], m-contiguous -> row-pairs pack free
    __shared__ float Bsd[16][132];   // Bsd[k][2*j..2*j+1] = {w, w} duplicated

    const int tid = threadIdx.x;
    const int tr = tid >> 4;         // 0..15 -> rows tr*8..tr*8+7
    const int tc = tid & 15;         // 0..15 -> cols tc*4..tc*4+3
    const int row0 = blockIdx.x * 128;

    unsigned long long acc[4][4];    // [row-pair][col]
    #pragma unroll
    for (int p = 0; p < 4; p++)
        #pragma unroll
        for (int j = 0; j < 4; j++) acc[p][j] = 0ULL;

    const unsigned as_base  = (unsigned)__cvta_generic_to_shared(&As[0][0]);
    const unsigned bsd_base = (unsigned)__cvta_generic_to_shared(&Bsd[0][0]);

    for (int k0 = 0; k0 < D; k0 += 16) {
        // A tile: 128 rows x 16 k = 512 float4, 2 per thread, store transposed
        #pragma unroll
        for (int i = 0; i < 2; i++) {
            int f4 = tid * 2 + i;
            int r  = f4 >> 2;
            int c4 = f4 & 3;
            int gr = row0 + r;
            float4 v = make_float4(0.f, 0.f, 0.f, 0.f);
            if (gr < N_NODES)
                v = __ldg(reinterpret_cast<const float4*>(x + (size_t)gr * D + k0 + c4 * 4));
            As[c4 * 4 + 0][r] = v.x;
            As[c4 * 4 + 1][r] = v.y;
            As[c4 * 4 + 2][r] = v.z;
            As[c4 * 4 + 3][r] = v.w;
        }
        // B tile: 16 k x 64 cols = 256 float4, 1 per thread, duplicated store
        {
            int r  = tid >> 4;       // k row 0..15
            int c4 = tid & 15;       // 4 cols
            float4 v = __ldg(reinterpret_cast<const float4*>(
                w + (size_t)(k0 + r) * D + h * 64 + c4 * 4));
            float* bp = &Bsd[r][c4 * 8];
            bp[0] = v.x; bp[1] = v.x;
            bp[2] = v.y; bp[3] = v.y;
            bp[4] = v.z; bp[5] = v.z;
            bp[6] = v.w; bp[7] = v.w;
        }
        __syncthreads();

        #pragma unroll
        for (int k = 0; k < 16; k++) {
            unsigned long long ap0, ap1, ap2, ap3, bp0, bp1, bp2, bp3;
            const unsigned aaddr = as_base  + (unsigned)((k * 132 + tr * 8) * 4);
            const unsigned baddr = bsd_base + (unsigned)((k * 132 + tc * 8) * 4);
            lds_v2u64(ap0, ap1, aaddr);          // rows {0,1},{2,3}
            lds_v2u64(ap2, ap3, aaddr + 16);     // rows {4,5},{6,7}
            lds_v2u64(bp0, bp1, baddr);          // cols {j0,j0},{j1,j1}
            lds_v2u64(bp2, bp3, baddr + 16);     // cols {j2,j2},{j3,j3}

            fma2(acc[0][0], ap0, bp0); fma2(acc[0][1], ap0, bp1);
            fma2(acc[0][2], ap0, bp2); fma2(acc[0][3], ap0, bp3);
            fma2(acc[1][0], ap1, bp0); fma2(acc[1][1], ap1, bp1);
            fma2(acc[1][2], ap1, bp2); fma2(acc[1][3], ap1, bp3);
            fma2(acc[2][0], ap2, bp0); fma2(acc[2][1], ap2, bp1);
            fma2(acc[2][2], ap2, bp2); fma2(acc[2][3], ap2, bp3);
            fma2(acc[3][0], ap3, bp0); fma2(acc[3][1], ap3, bp1);
            fma2(acc[3][2], ap3, bp2); fma2(acc[3][3], ap3, bp3);
        }
        __syncthreads();
    }

    // store: each row-pair p -> rows tr*8+2p, tr*8+2p+1
    #pragma unroll
    for (int p = 0; p < 4; p++) {
        float4 lo, hi;
        unpack2(lo.x, hi.x, acc[p][0]);
        unpack2(lo.y, hi.y, acc[p][1]);
        unpack2(lo.z, hi.z, acc[p][2]);
        unpack2(lo.w, hi.w, acc[p][3]);
        const int r0 = row0 + tr * 8 + 2 * p;
        float* dst = sup + (size_t)r0 * D + h * 64 + tc * 4;
        if (r0 < N_NODES)     *reinterpret_cast<float4*>(dst)     = lo;
        if (r0 + 1 < N_NODES) *reinterpret_cast<float4*>(dst + D) = hi;
    }
}

// ---------------------------------------------------------------------------
// Kernel 3: gather-aggregate over a feature half. One HALF-warp (16 lanes)
// per node; lane owns a float4 (16 lanes x 4 = 64 features).
// ---------------------------------------------------------------------------
__global__ __launch_bounds__(256) void aggregate_half_kernel(
    const float* __restrict__ sup, const float* __restrict__ norm,
    const float* __restrict__ bias, float* __restrict__ out, int h)
{
    const int idx = blockIdx.x * blockDim.x + threadIdx.x;
    const int g = idx >> 4;                  // node (half-warp)
    const int l = idx & 15;                  // lane within half-warp
    if (g >= N_NODES) return;

    int deg = g_counts[g];
    if (deg > CAP) deg = CAP;
    const int2* ep = g_edges + (size_t)g * CAP;
    const float4* sup4 = reinterpret_cast<const float4*>(sup);
    const int fb = h * 16 + l;               // float4 index within a row

    float4 acc = make_float4(0.f, 0.f, 0.f, 0.f);

    for (int j = 0; j < deg; j += 8) {
        int   c[8];
        float v[8];
        #pragma unroll
        for (int k = 0; k < 8; k++) {
            int2 p = __ldg(ep + j + k);      // uniform per half-warp -> broadcast
            bool ok = (j + k) < deg;
            c[k] = ok ? p.x : 0;
            v[k] = ok ? __int_as_float(p.y) : 0.0f;
        }
        float4 s[8];
        #pragma unroll
        for (int k = 0; k < 8; k++)
            s[k] = __ldg(sup4 + (size_t)c[k] * 32 + fb);
        #pragma unroll
        for (int k = 0; k < 8; k++) {
            acc.x = fmaf(s[k].x, v[k], acc.x);
            acc.y = fmaf(s[k].y, v[k], acc.y);
            acc.z = fmaf(s[k].z, v[k], acc.z);
            acc.w = fmaf(s[k].w, v[k], acc.w);
        }
    }

    const float inv = 1.0f / __ldg(norm + g);
    const float4 b = __ldg(reinterpret_cast<const float4*>(bias) + fb);
    float4 o;
    o.x = fmaf(acc.x, inv, b.x);
    o.y = fmaf(acc.y, inv, b.y);
    o.z = fmaf(acc.z, inv, b.z);
    o.w = fmaf(acc.w, inv, b.w);
    reinterpret_cast<float4*>(out)[(size_t)g * 32 + fb] = o;
}

// ---------------------------------------------------------------------------
extern "C" void kernel_launch(void* const* d_in, const int* in_sizes, int n_in,
                              void* d_out, int out_size) {
    const float* x      = (const float*)d_in[0];
    const float* weight = (const float*)d_in[1];
    const float* bias   = (const float*)d_in[2];
    const int*   rows   = (const int*)  d_in[3];
    const int*   cols   = (const int*)  d_in[4];
    const float* vals   = (const float*)d_in[5];
    const float* norm   = (const float*)d_in[6];
    float*       out    = (float*)d_out;

    float* sup;   cudaGetSymbolAddress((void**)&sup, g_support);
    int*   cnts;  cudaGetSymbolAddress((void**)&cnts, g_counts);

    // one-time stream/event creation (host resources only; identical device
    // work is issued on every call)
    static cudaStream_t sGemm = nullptr;
    static cudaEvent_t evFork, evG0, evG1;
    if (!sGemm) {
        cudaStreamCreateWithFlags(&sGemm, cudaStreamNonBlocking);
        cudaEventCreateWithFlags(&evFork, cudaEventDisableTiming);
        cudaEventCreateWithFlags(&evG0,   cudaEventDisableTiming);
        cudaEventCreateWithFlags(&evG1,   cudaEventDisableTiming);
    }

    const int gemm_blocks = (N_NODES + 127) / 128;
    const int agg_blocks  = (N_NODES * 16 + 255) / 256;
    const int quads       = N_EDGES / 4;

    // fork: GEMM halves on side stream (independent of edge bucketing)
    cudaEventRecord(evFork, 0);
    cudaStreamWaitEvent(sGemm, evFork, 0);
    gemm_half_kernel<<<gemm_blocks, 256, 0, sGemm>>>(x, weight, sup, 0);
    cudaEventRecord(evG0, sGemm);
    gemm_half_kernel<<<gemm_blocks, 256, 0, sGemm>>>(x, weight, sup, 1);
    cudaEventRecord(evG1, sGemm);

    // default stream: bucket edges meanwhile
    cudaMemsetAsync(cnts, 0, N_NODES * sizeof(int));
    place_kernel<<<(quads + 255) / 256, 256>>>(rows, cols, vals);

    // join: aggregate each feature half as soon as its support half is ready
    cudaStreamWaitEvent(0, evG0, 0);
    aggregate_half_kernel<<<agg_blocks, 256>>>(sup, norm, bias, out, 0);
    cudaStreamWaitEvent(0, evG1, 0);
    aggregate_half_kernel<<<agg_blocks, 256>>>(sup, norm, bias, out, 1);
}

// round 5
// speedup vs baseline: 1.7152x; 1.5030x over previous
#include <cuda_runtime.h>
#include <cuda_fp16.h>
#include <cstdint>

// GraphConv: out = segment_sum((x@W)[cols] * vals, rows) / norm + bias
// Inputs: x[100000,128] w[128,128] bias[128] rows[3.2M] cols[3.2M] vals[3.2M] norm[100000,1]
// out: [100000,128] f32

#define N_NODES 100000
#define N_EDGES 3200000
#define D 128
#define CAP 128

// static device scratch (allocations banned)
__device__ __half g_support_h[(size_t)N_NODES * D];   // 25.6 MB (fp16 support)
__device__ int    g_counts[N_NODES];                  // 0.4 MB
__device__ int2   g_edges[(size_t)N_NODES * CAP];     // 102.4 MB {col, val_bits}

// ---------------------------------------------------------------------------
// packed f32x2 helpers
// ---------------------------------------------------------------------------
__device__ __forceinline__ void fma2(unsigned long long& c,
                                     unsigned long long a, unsigned long long b) {
    asm("fma.rn.f32x2 %0, %1, %2, %0;" : "+l"(c) : "l"(a), "l"(b));
}
__device__ __forceinline__ unsigned long long pack2(float v) {
    unsigned long long p;
    asm("mov.b64 %0, {%1, %1};" : "=l"(p) : "f"(v));
    return p;
}
__device__ __forceinline__ void unpack2(float& lo, float& hi, unsigned long long p) {
    asm("mov.b64 {%0,%1}, %2;" : "=f"(lo), "=f"(hi) : "l"(p));
}

// ---------------------------------------------------------------------------
// Kernel 1: bucket edges by destination. 4 edges/thread for MLP.
// ---------------------------------------------------------------------------
__global__ __launch_bounds__(256) void place_kernel(
    const int* __restrict__ rows, const int* __restrict__ cols,
    const float* __restrict__ vals)
{
    const int t = blockIdx.x * blockDim.x + threadIdx.x;
    if (t * 4 >= N_EDGES) return;

    const int4   r4 = __ldg(reinterpret_cast<const int4*>(rows) + t);
    const int4   c4 = __ldg(reinterpret_cast<const int4*>(cols) + t);
    const float4 v4 = __ldg(reinterpret_cast<const float4*>(vals) + t);

    const int s0 = atomicAdd(&g_counts[r4.x], 1);
    const int s1 = atomicAdd(&g_counts[r4.y], 1);
    const int s2 = atomicAdd(&g_counts[r4.z], 1);
    const int s3 = atomicAdd(&g_counts[r4.w], 1);

    if (s0 < CAP) g_edges[(size_t)r4.x * CAP + s0] = make_int2(c4.x, __float_as_int(v4.x));
    if (s1 < CAP) g_edges[(size_t)r4.y * CAP + s1] = make_int2(c4.y, __float_as_int(v4.y));
    if (s2 < CAP) g_edges[(size_t)r4.z * CAP + s2] = make_int2(c4.z, __float_as_int(v4.z));
    if (s3 < CAP) g_edges[(size_t)r4.w * CAP + s3] = make_int2(c4.w, __float_as_int(v4.w));
}

// ---------------------------------------------------------------------------
// Kernel 2: SGEMM with packed f32x2 FMA, fp16 output.
// support[M,128] = half(x[M,128] @ W[128,128])
// 128x128 tile, BK=16, 256 threads, micro-tile 8 rows (4 packed pairs) x 8 cols.
// A-pairs load directly as ulonglong2 (m-contiguous smem); B duplicated in regs.
// ---------------------------------------------------------------------------
__global__ __launch_bounds__(256) void gemm_kernel(
    const float* __restrict__ x, const float* __restrict__ w,
    __half* __restrict__ sup)
{
    __shared__ float As[16][132];    // As[k][m]
    __shared__ float Bs[16][132];    // Bs[k][n]

    const int tid = threadIdx.x;
    const int tr = tid >> 4;         // 0..15 -> rows tr*8..tr*8+7
    const int tc = tid & 15;         // 0..15 -> cols tc*8..tc*8+7
    const int row0 = blockIdx.x * 128;

    unsigned long long acc[4][8];    // [row-pair][col]
    #pragma unroll
    for (int p = 0; p < 4; p++)
        #pragma unroll
        for (int j = 0; j < 8; j++) acc[p][j] = 0ULL;

    for (int k0 = 0; k0 < D; k0 += 16) {
        // A tile: 128 rows x 16 k = 512 float4, 2 per thread, store transposed
        #pragma unroll
        for (int i = 0; i < 2; i++) {
            int f4 = tid * 2 + i;
            int r  = f4 >> 2;
            int c4 = f4 & 3;
            int gr = row0 + r;
            float4 v = make_float4(0.f, 0.f, 0.f, 0.f);
            if (gr < N_NODES)
                v = __ldg(reinterpret_cast<const float4*>(x + (size_t)gr * D + k0 + c4 * 4));
            As[c4 * 4 + 0][r] = v.x;
            As[c4 * 4 + 1][r] = v.y;
            As[c4 * 4 + 2][r] = v.z;
            As[c4 * 4 + 3][r] = v.w;
        }
        // B tile: 16 k x 128 cols = 512 float4, 2 per thread
        #pragma unroll
        for (int i = 0; i < 2; i++) {
            int f4 = tid * 2 + i;
            int r  = f4 >> 5;
            int c4 = f4 & 31;
            float4 v = __ldg(reinterpret_cast<const float4*>(w + (size_t)(k0 + r) * D + c4 * 4));
            *reinterpret_cast<float4*>(&Bs[r][c4 * 4]) = v;
        }
        __syncthreads();

        #pragma unroll
        for (int k = 0; k < 16; k++) {
            // A row-pairs: contiguous -> direct 16B loads, no packing
            ulonglong2 a01 = *reinterpret_cast<ulonglong2*>(&As[k][tr * 8]);
            ulonglong2 a23 = *reinterpret_cast<ulonglong2*>(&As[k][tr * 8 + 4]);
            // B: 8 scalars, duplicate-pack in registers
            float4 b0 = *reinterpret_cast<float4*>(&Bs[k][tc * 8]);
            float4 b1 = *reinterpret_cast<float4*>(&Bs[k][tc * 8 + 4]);
            unsigned long long bp[8] = {
                pack2(b0.x), pack2(b0.y), pack2(b0.z), pack2(b0.w),
                pack2(b1.x), pack2(b1.y), pack2(b1.z), pack2(b1.w)};
            unsigned long long ap[4] = {a01.x, a01.y, a23.x, a23.y};
            #pragma unroll
            for (int p = 0; p < 4; p++)
                #pragma unroll
                for (int j = 0; j < 8; j++)
                    fma2(acc[p][j], ap[p], bp[j]);
        }
        __syncthreads();
    }

    // store fp16: pair p -> rows 2p, 2p+1; 8 cols -> one 16B store per row
    #pragma unroll
    for (int p = 0; p < 4; p++) {
        float lo[8], hi[8];
        #pragma unroll
        for (int j = 0; j < 8; j++) unpack2(lo[j], hi[j], acc[p][j]);

        __half2 hlo[4], hhi[4];
        #pragma unroll
        for (int q = 0; q < 4; q++) {
            hlo[q] = __floats2half2_rn(lo[2 * q], lo[2 * q + 1]);
            hhi[q] = __floats2half2_rn(hi[2 * q], hi[2 * q + 1]);
        }
        const int r0 = row0 + tr * 8 + 2 * p;
        __half* dst = sup + (size_t)r0 * D + tc * 8;
        if (r0 < N_NODES)
            *reinterpret_cast<uint4*>(dst) = *reinterpret_cast<uint4*>(hlo);
        if (r0 + 1 < N_NODES)
            *reinterpret_cast<uint4*>(dst + D) = *reinterpret_cast<uint4*>(hhi);
    }
}

// ---------------------------------------------------------------------------
// Kernel 3: gather-aggregate. One warp per node; lane owns 4 features (8B fp16).
// out[node] = (sum_e val_e * support[col_e]) / norm[node] + bias   (fp32 accum)
// ---------------------------------------------------------------------------
__global__ __launch_bounds__(256) void aggregate_kernel(
    const __half* __restrict__ sup, const float* __restrict__ norm,
    const float* __restrict__ bias, float* __restrict__ out)
{
    const int gwarp = (blockIdx.x * blockDim.x + threadIdx.x) >> 5;
    const int lane  = threadIdx.x & 31;
    if (gwarp >= N_NODES) return;

    int deg = g_counts[gwarp];
    if (deg > CAP) deg = CAP;
    const int2* ep = g_edges + (size_t)gwarp * CAP;
    const uint2* sup2 = reinterpret_cast<const uint2*>(sup);   // row = 32 uint2

    float4 acc = make_float4(0.f, 0.f, 0.f, 0.f);

    for (int j = 0; j < deg; j += 8) {
        int   c[8];
        float v[8];
        #pragma unroll
        for (int k = 0; k < 8; k++) {
            int2 p = __ldg(ep + j + k);          // warp-uniform broadcast
            bool ok = (j + k) < deg;
            c[k] = ok ? p.x : 0;
            v[k] = ok ? __int_as_float(p.y) : 0.0f;
        }
        uint2 s[8];
        #pragma unroll
        for (int k = 0; k < 8; k++)
            s[k] = __ldg(sup2 + (size_t)c[k] * 32 + lane);
        #pragma unroll
        for (int k = 0; k < 8; k++) {
            float2 f0 = __half22float2(*reinterpret_cast<__half2*>(&s[k].x));
            float2 f1 = __half22float2(*reinterpret_cast<__half2*>(&s[k].y));
            acc.x = fmaf(f0.x, v[k], acc.x);
            acc.y = fmaf(f0.y, v[k], acc.y);
            acc.z = fmaf(f1.x, v[k], acc.z);
            acc.w = fmaf(f1.y, v[k], acc.w);
        }
    }

    const float inv = 1.0f / __ldg(norm + gwarp);
    const float4 b = __ldg(reinterpret_cast<const float4*>(bias) + lane);
    float4 o;
    o.x = fmaf(acc.x, inv, b.x);
    o.y = fmaf(acc.y, inv, b.y);
    o.z = fmaf(acc.z, inv, b.z);
    o.w = fmaf(acc.w, inv, b.w);
    reinterpret_cast<float4*>(out)[(size_t)gwarp * 32 + lane] = o;
}

// ---------------------------------------------------------------------------
extern "C" void kernel_launch(void* const* d_in, const int* in_sizes, int n_in,
                              void* d_out, int out_size) {
    const float* x      = (const float*)d_in[0];
    const float* weight = (const float*)d_in[1];
    const float* bias   = (const float*)d_in[2];
    const int*   rows   = (const int*)  d_in[3];
    const int*   cols   = (const int*)  d_in[4];
    const float* vals   = (const float*)d_in[5];
    const float* norm   = (const float*)d_in[6];
    float*       out    = (float*)d_out;

    __half* sup;  cudaGetSymbolAddress((void**)&sup, g_support_h);
    int*    cnts; cudaGetSymbolAddress((void**)&cnts, g_counts);

    static cudaStream_t sGemm = nullptr;
    static cudaEvent_t evFork, evG;
    if (!sGemm) {
        cudaStreamCreateWithFlags(&sGemm, cudaStreamNonBlocking);
        cudaEventCreateWithFlags(&evFork, cudaEventDisableTiming);
        cudaEventCreateWithFlags(&evG,    cudaEventDisableTiming);
    }

    // fork: GEMM on side stream, concurrent with edge bucketing
    cudaEventRecord(evFork, 0);
    cudaStreamWaitEvent(sGemm, evFork, 0);
    gemm_kernel<<<(N_NODES + 127) / 128, 256, 0, sGemm>>>(x, weight, sup);
    cudaEventRecord(evG, sGemm);

    // default stream: bucket edges
    cudaMemsetAsync(cnts, 0, N_NODES * sizeof(int));
    place_kernel<<<(N_EDGES / 4 + 255) / 256, 256>>>(rows, cols, vals);

    // join, then aggregate
    cudaStreamWaitEvent(0, evG, 0);
    aggregate_kernel<<<(N_NODES * 32 + 255) / 256, 256>>>(sup, norm, bias, out);
}

// round 6
// speedup vs baseline: 2.2951x; 1.3381x over previous
#include <cuda_runtime.h>
#include <cuda_fp16.h>
#include <cstdint>

// GraphConv: out = segment_sum((x@W)[cols] * vals, rows) / norm + bias
// Inputs: x[100000,128] w[128,128] bias[128] rows[3.2M] cols[3.2M] vals[3.2M] norm[100000,1]
// out: [100000,128] f32

#define N_NODES 100000
#define N_EDGES 3200000
#define D 128
#define CAP 128

// static device scratch (allocations banned)
__device__ __half g_support_h[(size_t)N_NODES * D];   // 25.6 MB
__device__ int    g_counts[N_NODES];                  // 0.4 MB
__device__ int2   g_edges[(size_t)N_NODES * CAP];     // 102.4 MB {col, val_bits}

// ---------------------------------------------------------------------------
// mma / ldmatrix helpers
// ---------------------------------------------------------------------------
__device__ __forceinline__ uint32_t h2u(float a, float b) {
    __half2 h = __floats2half2_rn(a, b);
    return *reinterpret_cast<uint32_t*>(&h);
}
__device__ __forceinline__ void ldsm_x4(uint32_t& r0, uint32_t& r1, uint32_t& r2,
                                        uint32_t& r3, uint32_t addr) {
    asm volatile("ldmatrix.sync.aligned.m8n8.x4.shared.b16 {%0,%1,%2,%3}, [%4];"
                 : "=r"(r0), "=r"(r1), "=r"(r2), "=r"(r3) : "r"(addr));
}
__device__ __forceinline__ void ldsm_x4_t(uint32_t& r0, uint32_t& r1, uint32_t& r2,
                                          uint32_t& r3, uint32_t addr) {
    asm volatile("ldmatrix.sync.aligned.m8n8.x4.trans.shared.b16 {%0,%1,%2,%3}, [%4];"
                 : "=r"(r0), "=r"(r1), "=r"(r2), "=r"(r3) : "r"(addr));
}
__device__ __forceinline__ void mma16816(float* c, uint32_t a0, uint32_t a1,
                                         uint32_t a2, uint32_t a3,
                                         uint32_t b0, uint32_t b1) {
    asm volatile(
        "mma.sync.aligned.m16n8k16.row.col.f32.f16.f16.f32 "
        "{%0,%1,%2,%3}, {%4,%5,%6,%7}, {%8,%9}, {%0,%1,%2,%3};"
        : "+f"(c[0]), "+f"(c[1]), "+f"(c[2]), "+f"(c[3])
        : "r"(a0), "r"(a1), "r"(a2), "r"(a3), "r"(b0), "r"(b1));
}
// smem tile addressing: rows of 256B (128 halves) = 16 chunks of 16B,
// chunk XOR-swizzled by (row & 7) -> ldmatrix conflict-free.
__device__ __forceinline__ uint32_t tile_off(int row, int chunk) {
    return (uint32_t)(row * 256 + ((chunk ^ (row & 7)) << 4));
}

// ---------------------------------------------------------------------------
// Kernel 1: bucket edges by destination. 4 edges/thread.
// ---------------------------------------------------------------------------
__global__ __launch_bounds__(256) void place_kernel(
    const int* __restrict__ rows, const int* __restrict__ cols,
    const float* __restrict__ vals)
{
    const int t = blockIdx.x * blockDim.x + threadIdx.x;
    if (t * 4 >= N_EDGES) return;

    const int4   r4 = __ldg(reinterpret_cast<const int4*>(rows) + t);
    const int4   c4 = __ldg(reinterpret_cast<const int4*>(cols) + t);
    const float4 v4 = __ldg(reinterpret_cast<const float4*>(vals) + t);

    const int s0 = atomicAdd(&g_counts[r4.x], 1);
    const int s1 = atomicAdd(&g_counts[r4.y], 1);
    const int s2 = atomicAdd(&g_counts[r4.z], 1);
    const int s3 = atomicAdd(&g_counts[r4.w], 1);

    if (s0 < CAP) g_edges[(size_t)r4.x * CAP + s0] = make_int2(c4.x, __float_as_int(v4.x));
    if (s1 < CAP) g_edges[(size_t)r4.y * CAP + s1] = make_int2(c4.y, __float_as_int(v4.y));
    if (s2 < CAP) g_edges[(size_t)r4.z * CAP + s2] = make_int2(c4.z, __float_as_int(v4.z));
    if (s3 < CAP) g_edges[(size_t)r4.w * CAP + s3] = make_int2(c4.w, __float_as_int(v4.w));
}

// ---------------------------------------------------------------------------
// Kernel 2: tensor-core GEMM. support = half(x @ W), fp32 accum.
// Block: 128 rows, 256 threads (8 warps, m16 each). Full K=128 staged in smem:
//   A tile 128x128 fp16 (32KB, swizzled) + W tile 128x128 fp16 (32KB, swizzled).
// Per warp: 8 k-steps x (1 A-ldmatrix.x4 + 8 B-ldmatrix.x4.trans + 16 HMMA).
// ---------------------------------------------------------------------------
__global__ __launch_bounds__(256) void gemm_kernel(
    const float* __restrict__ x, const float* __restrict__ w,
    __half* __restrict__ sup)
{
    extern __shared__ char smem[];
    const uint32_t aBase = (uint32_t)__cvta_generic_to_shared(smem);
    const uint32_t wBase = aBase + 32768;

    const int tid  = threadIdx.x;
    const int warp = tid >> 5;
    const int lane = tid & 31;
    const int row0 = blockIdx.x * 128;

    // --- stage A (x rows, fp32->fp16) and W (fp32->fp16), swizzled ---
    #pragma unroll
    for (int i = 0; i < 8; i++) {
        const int ch   = tid + i * 256;        // 0..2047
        const int row  = ch >> 4;
        const int chk  = ch & 15;
        // A
        float4 f0 = make_float4(0.f, 0.f, 0.f, 0.f), f1 = f0;
        const int gr = row0 + row;
        if (gr < N_NODES) {
            const float* p = x + (size_t)gr * D + chk * 8;
            f0 = __ldg(reinterpret_cast<const float4*>(p));
            f1 = __ldg(reinterpret_cast<const float4*>(p + 4));
        }
        uint4 ua = make_uint4(h2u(f0.x, f0.y), h2u(f0.z, f0.w),
                              h2u(f1.x, f1.y), h2u(f1.z, f1.w));
        *reinterpret_cast<uint4*>(smem + tile_off(row, chk)) = ua;
        // W
        const float* q = w + (size_t)row * D + chk * 8;
        float4 g0 = __ldg(reinterpret_cast<const float4*>(q));
        float4 g1 = __ldg(reinterpret_cast<const float4*>(q + 4));
        uint4 uw = make_uint4(h2u(g0.x, g0.y), h2u(g0.z, g0.w),
                              h2u(g1.x, g1.y), h2u(g1.z, g1.w));
        *reinterpret_cast<uint4*>(smem + 32768 + tile_off(row, chk)) = uw;
    }
    __syncthreads();

    // --- compute ---
    float acc[16][4];
    #pragma unroll
    for (int t = 0; t < 16; t++)
        #pragma unroll
        for (int j = 0; j < 4; j++) acc[t][j] = 0.0f;

    const int lm = lane & 15;          // row-within-16 for ldmatrix
    const int lh = lane >> 4;          // chunk selector
    const int m7 = lm & 7;

    #pragma unroll
    for (int ks = 0; ks < 8; ks++) {
        uint32_t a0, a1, a2, a3;
        ldsm_x4(a0, a1, a2, a3,
                aBase + tile_off(warp * 16 + lm, 2 * ks + lh));
        #pragma unroll
        for (int nt2 = 0; nt2 < 8; nt2++) {
            uint32_t b0, b1, b2, b3;
            ldsm_x4_t(b0, b1, b2, b3,
                      wBase + tile_off(ks * 16 + lm, nt2 * 2 + lh));
            mma16816(acc[nt2 * 2 + 0], a0, a1, a2, a3, b0, b1);
            mma16816(acc[nt2 * 2 + 1], a0, a1, a2, a3, b2, b3);
        }
    }

    // --- store fp16 ---
    const int cr = lane >> 2;          // 0..7
    const int cc = (lane & 3) * 2;     // 0,2,4,6
    const int r0 = row0 + warp * 16 + cr;
    const int r1 = r0 + 8;
    #pragma unroll
    for (int nt = 0; nt < 16; nt++) {
        uint32_t p0 = h2u(acc[nt][0], acc[nt][1]);
        uint32_t p1 = h2u(acc[nt][2], acc[nt][3]);
        if (r0 < N_NODES)
            *reinterpret_cast<uint32_t*>(sup + (size_t)r0 * D + nt * 8 + cc) = p0;
        if (r1 < N_NODES)
            *reinterpret_cast<uint32_t*>(sup + (size_t)r1 * D + nt * 8 + cc) = p1;
    }
}

// ---------------------------------------------------------------------------
// Kernel 3: gather-aggregate. One HALF-warp per node; lane owns 8 fp16 (16B).
// out[node] = (sum_e val_e * support[col_e]) / norm[node] + bias  (fp32 accum)
// ---------------------------------------------------------------------------
__global__ __launch_bounds__(256) void aggregate_kernel(
    const __half* __restrict__ sup, const float* __restrict__ norm,
    const float* __restrict__ bias, float* __restrict__ out)
{
    const int idx = blockIdx.x * blockDim.x + threadIdx.x;
    const int g = idx >> 4;
    const int l = idx & 15;
    if (g >= N_NODES) return;

    int deg = g_counts[g];
    if (deg > CAP) deg = CAP;
    const int2* ep = g_edges + (size_t)g * CAP;
    const uint4* sup4 = reinterpret_cast<const uint4*>(sup);  // row = 16 uint4

    float acc[8] = {0.f, 0.f, 0.f, 0.f, 0.f, 0.f, 0.f, 0.f};

    for (int j = 0; j < deg; j += 8) {
        int   c[8];
        float v[8];
        #pragma unroll
        for (int k = 0; k < 8; k++) {
            int2 p = __ldg(ep + j + k);          // uniform per half-warp
            bool ok = (j + k) < deg;
            c[k] = ok ? p.x : 0;
            v[k] = ok ? __int_as_float(p.y) : 0.0f;
        }
        uint4 s[8];
        #pragma unroll
        for (int k = 0; k < 8; k++)
            s[k] = __ldg(sup4 + (size_t)c[k] * 16 + l);
        #pragma unroll
        for (int k = 0; k < 8; k++) {
            float2 f0 = __half22float2(*reinterpret_cast<__half2*>(&s[k].x));
            float2 f1 = __half22float2(*reinterpret_cast<__half2*>(&s[k].y));
            float2 f2 = __half22float2(*reinterpret_cast<__half2*>(&s[k].z));
            float2 f3 = __half22float2(*reinterpret_cast<__half2*>(&s[k].w));
            acc[0] = fmaf(f0.x, v[k], acc[0]);
            acc[1] = fmaf(f0.y, v[k], acc[1]);
            acc[2] = fmaf(f1.x, v[k], acc[2]);
            acc[3] = fmaf(f1.y, v[k], acc[3]);
            acc[4] = fmaf(f2.x, v[k], acc[4]);
            acc[5] = fmaf(f2.y, v[k], acc[5]);
            acc[6] = fmaf(f3.x, v[k], acc[6]);
            acc[7] = fmaf(f3.y, v[k], acc[7]);
        }
    }

    const float inv = 1.0f / __ldg(norm + g);
    const float4 b0 = __ldg(reinterpret_cast<const float4*>(bias) + l * 2);
    const float4 b1 = __ldg(reinterpret_cast<const float4*>(bias) + l * 2 + 1);
    float4 o0, o1;
    o0.x = fmaf(acc[0], inv, b0.x);
    o0.y = fmaf(acc[1], inv, b0.y);
    o0.z = fmaf(acc[2], inv, b0.z);
    o0.w = fmaf(acc[3], inv, b0.w);
    o1.x = fmaf(acc[4], inv, b1.x);
    o1.y = fmaf(acc[5], inv, b1.y);
    o1.z = fmaf(acc[6], inv, b1.z);
    o1.w = fmaf(acc[7], inv, b1.w);
    float4* dst = reinterpret_cast<float4*>(out) + (size_t)g * 32 + l * 2;
    dst[0] = o0;
    dst[1] = o1;
}

// ---------------------------------------------------------------------------
extern "C" void kernel_launch(void* const* d_in, const int* in_sizes, int n_in,
                              void* d_out, int out_size) {
    const float* x      = (const float*)d_in[0];
    const float* weight = (const float*)d_in[1];
    const float* bias   = (const float*)d_in[2];
    const int*   rows   = (const int*)  d_in[3];
    const int*   cols   = (const int*)  d_in[4];
    const float* vals   = (const float*)d_in[5];
    const float* norm   = (const float*)d_in[6];
    float*       out    = (float*)d_out;

    __half* sup;  cudaGetSymbolAddress((void**)&sup, g_support_h);
    int*    cnts; cudaGetSymbolAddress((void**)&cnts, g_counts);

    static cudaStream_t sGemm = nullptr;
    static cudaEvent_t evFork, evG;
    if (!sGemm) {
        cudaStreamCreateWithFlags(&sGemm, cudaStreamNonBlocking);
        cudaEventCreateWithFlags(&evFork, cudaEventDisableTiming);
        cudaEventCreateWithFlags(&evG,    cudaEventDisableTiming);
        cudaFuncSetAttribute(gemm_kernel,
                             cudaFuncAttributeMaxDynamicSharedMemorySize, 65536);
    }

    // fork: tensor-core GEMM on side stream, concurrent with edge bucketing
    cudaEventRecord(evFork, 0);
    cudaStreamWaitEvent(sGemm, evFork, 0);
    gemm_kernel<<<(N_NODES + 127) / 128, 256, 65536, sGemm>>>(x, weight, sup);
    cudaEventRecord(evG, sGemm);

    // default stream: bucket edges
    cudaMemsetAsync(cnts, 0, N_NODES * sizeof(int));
    place_kernel<<<(N_EDGES / 4 + 255) / 256, 256>>>(rows, cols, vals);

    // join, then aggregate (half-warp per node)
    cudaStreamWaitEvent(0, evG, 0);
    aggregate_kernel<<<(N_NODES * 16 + 255) / 256, 256>>>(sup, norm, bias, out);
}